// round 14
// baseline (speedup 1.0000x reference)
#include <cuda_runtime.h>
#include <cuda_bf16.h>
#include <stdint.h>
#include <math.h>

#define NB 4096
#define NP 32
#define NC 512
#define NT2 32                          // 4096/128 tile grid for ii
#define NBLK_II (NT2 * (NT2 + 1) / 2)   // 528 upper-triangle tiles
#define SAW 72                          // padded smem row (bf16) for ii tiles
#define BUFSZ (128 * SAW * 2)           // bytes per 128x64 bf16 buffer
#define SPW 520                         // padded smem row (bf16) for pivot matrix
#define NWORK (NB + NBLK_II)            // merged grid: 4624

__device__ double g_acc[4];                 // [0]=ii, [1]=tt, [2]=it, [3]=mae
__device__ unsigned int g_cnt;              // blocks-done counter (self-resetting)
__device__ __nv_bfloat16 g_fnh[NB * NC];    // L2-normalized feats, bf16

__device__ __forceinline__ float warp_sum(float v) {
#pragma unroll
    for (int o = 16; o > 0; o >>= 1) v += __shfl_xor_sync(0xffffffffu, v, o);
    return v;
}

__device__ __forceinline__ void ldsm4(uint32_t* r, uint32_t addr) {
    asm volatile("ldmatrix.sync.aligned.m8n8.x4.shared.b16 {%0,%1,%2,%3}, [%4];"
                 : "=r"(r[0]), "=r"(r[1]), "=r"(r[2]), "=r"(r[3]) : "r"(addr));
}

__device__ __forceinline__ void mma_bf16(float* d, const uint32_t* a,
                                         uint32_t b0, uint32_t b1) {
    asm volatile(
        "mma.sync.aligned.m16n8k16.row.col.f32.bf16.bf16.f32 "
        "{%0,%1,%2,%3}, {%4,%5,%6,%7}, {%8,%9}, {%0,%1,%2,%3};"
        : "+f"(d[0]), "+f"(d[1]), "+f"(d[2]), "+f"(d[3])
        : "r"(a[0]), "r"(a[1]), "r"(a[2]), "r"(a[3]), "r"(b0), "r"(b1));
}

__device__ __forceinline__ void cp16(uint32_t saddr, const void* gptr) {
    asm volatile("cp.async.cg.shared.global [%0], [%1], 16;"
                 :: "r"(saddr), "l"(gptr) : "memory");
}
#define CP_COMMIT() asm volatile("cp.async.commit_group;" ::: "memory")
#define CP_WAIT(N)  asm volatile("cp.async.wait_group %0;" :: "n"(N) : "memory")

// One block per feats row: L2-normalize, write bf16 row. Block 0 also
// zeroes the loss accumulators (runs before k_work on the same stream).
__global__ void k_norm_feats(const float* __restrict__ feats) {
    __shared__ float red[4];
    int b = blockIdx.x, t = threadIdx.x;  // 128 threads, 128 float4/row
    if (b == 0 && t < 4) g_acc[t] = 0.0;
    const float4* src = (const float4*)(feats + (size_t)b * NC);
    float4 v = src[t];
    float s = v.x * v.x + v.y * v.y + v.z * v.z + v.w * v.w;
    s = warp_sum(s);
    if ((t & 31) == 0) red[t >> 5] = s;
    __syncthreads();
    float tot = red[0] + red[1] + red[2] + red[3];
    float inv = 1.0f / fmaxf(sqrtf(tot), 1e-12f);
    __nv_bfloat162* dst = (__nv_bfloat162*)(g_fnh + (size_t)b * NC);
    dst[2 * t]     = __floats2bfloat162_rn(v.x * inv, v.y * inv);
    dst[2 * t + 1] = __floats2bfloat162_rn(v.z * inv, v.w * inv);
}

// ---------------- pivot body (one block per batch b) ----------------
__device__ __forceinline__ void pivot_body(int b, char* smraw,
                                           const float* __restrict__ pf,
                                           const float* __restrict__ ps,
                                           const float* __restrict__ targets,
                                           const float* __restrict__ pred) {
    __nv_bfloat16* pfh = (__nv_bfloat16*)smraw;                  // 32 * SPW raw bf16
    __nv_bfloat16* fr  = (__nv_bfloat16*)(smraw + 32 * SPW * 2); // 512 normalized feat row
    float* part = (float*)(smraw + 32 * SPW * 2 + NC * 2);       // 4 * 1024
    float* ps_s = part + 4096;                                   // 32
    float* sinv = ps_s + 32;                                     // 32
    float* red  = sinv + 32;                                     // 16

    int tid = threadIdx.x, lane = tid & 31, w = tid >> 5;

    if (tid < 32) ps_s[tid] = ps[b * NP + tid];
    if (tid < 64)
        ((uint4*)fr)[tid] = ((const uint4*)(g_fnh + (size_t)b * NC))[tid];

    // load pivot rows raw (all 16 LDG.128 upfront), norms, store bf16 + sinv.
    {
        float4 vals[4][4];
#pragma unroll
        for (int rr = 0; rr < 4; rr++) {
            int p = w + rr * 8;
            const float4* src4 = (const float4*)(pf + ((size_t)b * NP + p) * NC);
#pragma unroll
            for (int t = 0; t < 4; t++) vals[rr][t] = src4[lane + 32 * t];
        }
        float sums[4];
#pragma unroll
        for (int rr = 0; rr < 4; rr++) {
            float s = 0.f;
#pragma unroll
            for (int t = 0; t < 4; t++) {
                float4 v = vals[rr][t];
                s += v.x * v.x + v.y * v.y + v.z * v.z + v.w * v.w;
            }
            sums[rr] = warp_sum(s);
        }
#pragma unroll
        for (int rr = 0; rr < 4; rr++) {
            int p = w + rr * 8;
            __nv_bfloat162* dst = (__nv_bfloat162*)(pfh + p * SPW);
#pragma unroll
            for (int t = 0; t < 4; t++) {
                float4 v = vals[rr][t];
                int i = lane + 32 * t;
                dst[2 * i]     = __floats2bfloat162_rn(v.x, v.y);
                dst[2 * i + 1] = __floats2bfloat162_rn(v.z, v.w);
            }
            if (lane == 0) sinv[p] = 1.0f / fmaxf(sqrtf(sums[rr]), 1e-12f);
        }
    }
    __syncthreads();

    float tb = targets[b];
    if (w < 4) {
        // gram: warp w owns k-slice [128w, 128w+128), 32x32 raw gram
        uint32_t base = (uint32_t)__cvta_generic_to_shared(pfh);
        int kslice = w * 128;
        int w8 = lane & 7;
        uint32_t aAddr[2], bAddr[2];
#pragma unroll
        for (int m = 0; m < 2; m++) {
            int row  = 16 * m + ((lane >> 3) & 1) * 8 + w8;
            int koff = (lane >> 4) * 8;
            aAddr[m] = base + (uint32_t)(row * SPW + kslice + koff) * 2;
        }
#pragma unroll
        for (int p = 0; p < 2; p++) {
            int col  = 16 * p + ((lane >> 4) & 1) * 8 + w8;
            int koff = ((lane >> 3) & 1) * 8;
            bAddr[p] = base + (uint32_t)(col * SPW + kslice + koff) * 2;
        }
        float acc[2][4][4] = {};
#pragma unroll
        for (int ks = 0; ks < 8; ks++) {
            uint32_t a[2][4], bb[2][4];
#pragma unroll
            for (int m = 0; m < 2; m++) ldsm4(a[m], aAddr[m] + ks * 32);
#pragma unroll
            for (int p = 0; p < 2; p++) ldsm4(bb[p], bAddr[p] + ks * 32);
#pragma unroll
            for (int m = 0; m < 2; m++) {
#pragma unroll
                for (int n = 0; n < 4; n++) {
                    mma_bf16(acc[m][n], a[m], bb[n >> 1][(n & 1) * 2],
                             bb[n >> 1][(n & 1) * 2 + 1]);
                }
            }
        }
        float* my = part + w * 1024;
#pragma unroll
        for (int m = 0; m < 2; m++) {
#pragma unroll
            for (int n = 0; n < 4; n++) {
                int r0 = 16 * m + (lane >> 2);
                int c0 = 8 * n + 2 * (lane & 3);
                my[r0 * 32 + c0]           = acc[m][n][0];
                my[r0 * 32 + c0 + 1]       = acc[m][n][1];
                my[(r0 + 8) * 32 + c0]     = acc[m][n][2];
                my[(r0 + 8) * 32 + c0 + 1] = acc[m][n][3];
            }
        }
    } else {
        // it-dots: warp w (4..7) handles pivots (w-4)*8 .. (w-4)*8+7
        const uint32_t* fr2 = (const uint32_t*)fr;
        float itv = 0.f;
#pragma unroll
        for (int r = 0; r < 8; r++) {
            int p = (w - 4) * 8 + r;
            const uint32_t* pf2 = (const uint32_t*)(pfh + p * SPW);
            float s = 0.f;
#pragma unroll
            for (int t = 0; t < 8; t++) {
                float2 a2 = __bfloat1622float2(*(const __nv_bfloat162*)&fr2[lane + 32 * t]);
                float2 b2 = __bfloat1622float2(*(const __nv_bfloat162*)&pf2[lane + 32 * t]);
                s += a2.x * b2.x + a2.y * b2.y;
            }
            s = warp_sum(s);
            if (lane == 0)
                itv += fabsf(s * sinv[p] - (1.f - 0.1f * fabsf(tb - ps_s[p])));
        }
        if (lane == 0) red[8 + (w - 4)] = itv;
    }
    __syncthreads();

    // epilogue: sum 4 partials, scale by inv_p*inv_q, tt loss
    float tt = 0.f;
#pragma unroll
    for (int k = 0; k < 4; k++) {
        int e = tid + 256 * k;  // 0..1023
        int p = e >> 5, q = e & 31;
        float s = (part[e] + part[1024 + e] + part[2048 + e] + part[3072 + e])
                * sinv[p] * sinv[q];
        tt += fabsf(s - (1.f - 0.1f * fabsf(ps_s[p] - ps_s[q])));
    }
    tt = warp_sum(tt);
    if (lane == 0) red[w] = tt;
    __syncthreads();
    if (tid == 0) {
        float t0 = 0.f, t1 = 0.f;
#pragma unroll
        for (int i = 0; i < 8; i++) t0 += red[i];
#pragma unroll
        for (int i = 0; i < 4; i++) t1 += red[8 + i];
        atomicAdd(&g_acc[1], (double)t0);
        atomicAdd(&g_acc[2], (double)t1);
        atomicAdd(&g_acc[3], (double)fabsf(pred[b] - tb));   // mae term
    }
}

// ---------------- ii body (one block per 128x128 tile) ----------------
__device__ __forceinline__ void ii_body(int tileIdx, char* smraw,
                                        const float* __restrict__ targets) {
    __nv_bfloat16* sm = (__nv_bfloat16*)smraw;   // As0|As1|Bs0|Bs1
    __shared__ float tr[128], tc[128], red2[8];

    int idx = tileIdx, bi = 0;
    while (true) {
        int len = NT2 - bi;
        if (idx < len) break;
        idx -= len; bi++;
    }
    int bj = bi + idx;

    int tid = threadIdx.x, lane = tid & 31, w = tid >> 5;
    if (tid < 128) tr[tid]       = targets[bi * 128 + tid];
    else           tc[tid - 128] = targets[bj * 128 + (tid - 128)];

    uint32_t smBase = (uint32_t)__cvta_generic_to_shared(sm);
    const __nv_bfloat16* Ag = g_fnh + (size_t)(bi * 128) * NC;
    const __nv_bfloat16* Bg = g_fnh + (size_t)(bj * 128) * NC;

    int crow[4], cch[4];
#pragma unroll
    for (int i = 0; i < 4; i++) {
        int c = tid + 256 * i;
        crow[i] = c >> 3;
        cch[i]  = (c & 7) * 8;
    }

    int wy = w >> 1, wx = w & 1;   // warp grid 4x2, warp tile 32x64
    int w8 = lane & 7;
    uint32_t aOff[2], bOff[4];
#pragma unroll
    for (int m = 0; m < 2; m++) {
        int row  = 32 * wy + 16 * m + ((lane >> 3) & 1) * 8 + w8;
        int koff = (lane >> 4) * 8;
        aOff[m] = (uint32_t)(row * SAW + koff) * 2;
    }
#pragma unroll
    for (int p = 0; p < 4; p++) {
        int col  = 64 * wx + 16 * p + ((lane >> 4) & 1) * 8 + w8;
        int koff = ((lane >> 3) & 1) * 8;
        bOff[p] = (uint32_t)(col * SAW + koff) * 2;
    }

#pragma unroll
    for (int s = 0; s < 2; s++) {
        uint32_t abase = smBase + s * BUFSZ;
        uint32_t bbase = smBase + 2 * BUFSZ + s * BUFSZ;
        int k0 = s * 64;
#pragma unroll
        for (int i = 0; i < 4; i++) {
            cp16(abase + (uint32_t)(crow[i] * SAW + cch[i]) * 2,
                 Ag + (size_t)crow[i] * NC + k0 + cch[i]);
            cp16(bbase + (uint32_t)(crow[i] * SAW + cch[i]) * 2,
                 Bg + (size_t)crow[i] * NC + k0 + cch[i]);
        }
        CP_COMMIT();
    }

    float acc[2][8][4] = {};
#pragma unroll
    for (int k0 = 0; k0 < 8; k0++) {
        if (k0 == 7) { CP_WAIT(0); } else { CP_WAIT(1); }
        __syncthreads();
        int buf = k0 & 1;
        uint32_t abase = smBase + buf * BUFSZ;
        uint32_t bbase = smBase + 2 * BUFSZ + buf * BUFSZ;
#pragma unroll
        for (int ks = 0; ks < 4; ks++) {
            uint32_t a[2][4], bb[4][4];
#pragma unroll
            for (int m = 0; m < 2; m++) ldsm4(a[m], abase + aOff[m] + ks * 32);
#pragma unroll
            for (int p = 0; p < 4; p++) ldsm4(bb[p], bbase + bOff[p] + ks * 32);
#pragma unroll
            for (int m = 0; m < 2; m++) {
#pragma unroll
                for (int n = 0; n < 8; n++) {
                    mma_bf16(acc[m][n], a[m], bb[n >> 1][(n & 1) * 2],
                             bb[n >> 1][(n & 1) * 2 + 1]);
                }
            }
        }
        __syncthreads();
        if (k0 + 2 < 8) {
            int s = k0 + 2, kk = s * 64, nbuf = s & 1;
            uint32_t na = smBase + nbuf * BUFSZ;
            uint32_t nb = smBase + 2 * BUFSZ + nbuf * BUFSZ;
#pragma unroll
            for (int i = 0; i < 4; i++) {
                cp16(na + (uint32_t)(crow[i] * SAW + cch[i]) * 2,
                     Ag + (size_t)crow[i] * NC + kk + cch[i]);
                cp16(nb + (uint32_t)(crow[i] * SAW + cch[i]) * 2,
                     Bg + (size_t)crow[i] * NC + kk + cch[i]);
            }
            CP_COMMIT();
        }
    }

    float lsum = 0.f;
#pragma unroll
    for (int m = 0; m < 2; m++) {
#pragma unroll
        for (int n = 0; n < 8; n++) {
            int r0 = 32 * wy + 16 * m + (lane >> 2);
            int c0 = 64 * wx + 8 * n + 2 * (lane & 3);
            float tr0 = tr[r0], tr8 = tr[r0 + 8];
            float tc0 = tc[c0], tc1 = tc[c0 + 1];
            lsum += fabsf(acc[m][n][0] - (1.f - 0.1f * fabsf(tr0 - tc0)));
            lsum += fabsf(acc[m][n][1] - (1.f - 0.1f * fabsf(tr0 - tc1)));
            lsum += fabsf(acc[m][n][2] - (1.f - 0.1f * fabsf(tr8 - tc0)));
            lsum += fabsf(acc[m][n][3] - (1.f - 0.1f * fabsf(tr8 - tc1)));
        }
    }
    lsum = warp_sum(lsum);
    if (lane == 0) red2[w] = lsum;
    __syncthreads();
    if (tid == 0) {
        float wgt = (bi == bj) ? 1.f : 2.f;
        float t0 = 0.f;
#pragma unroll
        for (int i = 0; i < 8; i++) t0 += red2[i];
        atomicAdd(&g_acc[0], (double)(t0 * wgt));
    }
}

// Merged kernel: ii tiles interleaved 1-in-8 with pivot blocks; the block
// that finishes last writes the 4 outputs (no separate final kernel).
__global__ void __launch_bounds__(256, 2) k_work(const float* __restrict__ pf,
                                                 const float* __restrict__ ps,
                                                 const float* __restrict__ targets,
                                                 const float* __restrict__ pred,
                                                 float* __restrict__ out) {
    extern __shared__ char smraw[];
    int bid = blockIdx.x;
    int iiId = bid >> 3;
    if ((bid & 7) == 7 && iiId < NBLK_II) {
        ii_body(iiId, smraw, targets);
    } else {
        int nIIBefore = (bid + 1) >> 3;
        if (nIIBefore > NBLK_II) nIIBefore = NBLK_II;
        int pid = bid - nIIBefore;
        pivot_body(pid, smraw, pf, ps, targets, pred);
    }

    // last-block-done epilogue
    __threadfence();
    __syncthreads();
    if (threadIdx.x == 0) {
        unsigned int done = atomicAdd(&g_cnt, 1u);
        if (done == NWORK - 1) {
            double ii  = atomicAdd(&g_acc[0], 0.0);
            double tt  = atomicAdd(&g_acc[1], 0.0);
            double it  = atomicAdd(&g_acc[2], 0.0);
            double mae = atomicAdd(&g_acc[3], 0.0);
            out[0] = (float)(ii  / ((double)NB * (double)NB));
            out[1] = (float)(tt  / ((double)NB * (double)NP * (double)NP));
            out[2] = (float)(it  / ((double)NB * (double)NP));
            out[3] = (float)(mae / (double)NB);
            g_cnt = 0;   // self-reset for graph replay
        }
    }
}

extern "C" void kernel_launch(void* const* d_in, const int* in_sizes, int n_in,
                              void* d_out, int out_size) {
    const float* pred    = (const float*)d_in[0];
    const float* targets = (const float*)d_in[1];
    const float* feats   = (const float*)d_in[2];
    const float* pivf    = (const float*)d_in[3];
    const float* pivs    = (const float*)d_in[4];
    float* out = (float*)d_out;

    size_t smWork = (size_t)(4 * BUFSZ);   // 73728 bytes (ii needs all; pivot ~51KB)
    cudaFuncSetAttribute(k_work, cudaFuncAttributeMaxDynamicSharedMemorySize, (int)smWork);

    k_norm_feats<<<NB, 128>>>(feats);
    k_work<<<NWORK, 256, smWork>>>(pivf, pivs, targets, pred, out);
}

// round 16
// speedup vs baseline: 1.0018x; 1.0018x over previous
#include <cuda_runtime.h>
#include <cuda_bf16.h>
#include <stdint.h>
#include <math.h>

#define NB 4096
#define NP 32
#define NC 512
#define NT2 32                          // 4096/128 tile grid for ii
#define NBLK_II (NT2 * (NT2 + 1) / 2)   // 528 upper-triangle tiles
#define SAW 72                          // padded smem row (bf16) for ii tiles
#define BUFSZ (128 * SAW * 2)           // bytes per 128x64 bf16 buffer
#define SPW 520                         // padded smem row (bf16) for pivot matrix
#define NWORK (NB + NBLK_II)            // merged grid: 4624

__device__ double g_acc[4];                 // [0]=ii, [1]=tt, [2]=it, [3]=mae
__device__ unsigned int g_cnt;              // blocks-done counter (self-resetting)
__device__ __nv_bfloat16 g_fnh[NB * NC];    // L2-normalized feats, bf16

__device__ __forceinline__ float warp_sum(float v) {
#pragma unroll
    for (int o = 16; o > 0; o >>= 1) v += __shfl_xor_sync(0xffffffffu, v, o);
    return v;
}

__device__ __forceinline__ void ldsm4(uint32_t* r, uint32_t addr) {
    asm volatile("ldmatrix.sync.aligned.m8n8.x4.shared.b16 {%0,%1,%2,%3}, [%4];"
                 : "=r"(r[0]), "=r"(r[1]), "=r"(r[2]), "=r"(r[3]) : "r"(addr));
}

__device__ __forceinline__ void mma_bf16(float* d, const uint32_t* a,
                                         uint32_t b0, uint32_t b1) {
    asm volatile(
        "mma.sync.aligned.m16n8k16.row.col.f32.bf16.bf16.f32 "
        "{%0,%1,%2,%3}, {%4,%5,%6,%7}, {%8,%9}, {%0,%1,%2,%3};"
        : "+f"(d[0]), "+f"(d[1]), "+f"(d[2]), "+f"(d[3])
        : "r"(a[0]), "r"(a[1]), "r"(a[2]), "r"(a[3]), "r"(b0), "r"(b1));
}

__device__ __forceinline__ void cp16(uint32_t saddr, const void* gptr) {
    asm volatile("cp.async.cg.shared.global [%0], [%1], 16;"
                 :: "r"(saddr), "l"(gptr) : "memory");
}
#define CP_COMMIT() asm volatile("cp.async.commit_group;" ::: "memory")
#define CP_WAIT(N)  asm volatile("cp.async.wait_group %0;" :: "n"(N) : "memory")

// One block per feats row: L2-normalize, write bf16 row. Block 0 also
// zeroes the loss accumulators (runs before k_work on the same stream).
__global__ void k_norm_feats(const float* __restrict__ feats) {
    __shared__ float red[4];
    int b = blockIdx.x, t = threadIdx.x;  // 128 threads, 128 float4/row
    if (b == 0 && t < 4) g_acc[t] = 0.0;
    const float4* src = (const float4*)(feats + (size_t)b * NC);
    float4 v = src[t];
    float s = v.x * v.x + v.y * v.y + v.z * v.z + v.w * v.w;
    s = warp_sum(s);
    if ((t & 31) == 0) red[t >> 5] = s;
    __syncthreads();
    float tot = red[0] + red[1] + red[2] + red[3];
    float inv = 1.0f / fmaxf(sqrtf(tot), 1e-12f);
    __nv_bfloat162* dst = (__nv_bfloat162*)(g_fnh + (size_t)b * NC);
    dst[2 * t]     = __floats2bfloat162_rn(v.x * inv, v.y * inv);
    dst[2 * t + 1] = __floats2bfloat162_rn(v.z * inv, v.w * inv);
}

// ---------------- pivot body (one block per batch b) ----------------
__device__ __forceinline__ void pivot_body(int b, char* smraw,
                                           const float* __restrict__ pf,
                                           const float* __restrict__ ps,
                                           const float* __restrict__ targets,
                                           const float* __restrict__ pred) {
    __nv_bfloat16* pfh = (__nv_bfloat16*)smraw;                  // 32 * SPW raw bf16
    __nv_bfloat16* fr  = (__nv_bfloat16*)(smraw + 32 * SPW * 2); // 512 normalized feat row
    float* part = (float*)(smraw + 32 * SPW * 2 + NC * 2);       // 4 * 1024
    float* ps_s = part + 4096;                                   // 32
    float* sinv = ps_s + 32;                                     // 32
    float* red  = sinv + 32;                                     // 16

    int tid = threadIdx.x, lane = tid & 31, w = tid >> 5;

    if (tid < 32) ps_s[tid] = ps[b * NP + tid];
    if (tid < 64)
        ((uint4*)fr)[tid] = ((const uint4*)(g_fnh + (size_t)b * NC))[tid];

    // load pivot rows raw (all 16 LDG.128 upfront), norms, store bf16 + sinv.
    {
        float4 vals[4][4];
#pragma unroll
        for (int rr = 0; rr < 4; rr++) {
            int p = w + rr * 8;
            const float4* src4 = (const float4*)(pf + ((size_t)b * NP + p) * NC);
#pragma unroll
            for (int t = 0; t < 4; t++) vals[rr][t] = src4[lane + 32 * t];
        }
        float sums[4];
#pragma unroll
        for (int rr = 0; rr < 4; rr++) {
            float s = 0.f;
#pragma unroll
            for (int t = 0; t < 4; t++) {
                float4 v = vals[rr][t];
                s += v.x * v.x + v.y * v.y + v.z * v.z + v.w * v.w;
            }
            sums[rr] = warp_sum(s);
        }
#pragma unroll
        for (int rr = 0; rr < 4; rr++) {
            int p = w + rr * 8;
            __nv_bfloat162* dst = (__nv_bfloat162*)(pfh + p * SPW);
#pragma unroll
            for (int t = 0; t < 4; t++) {
                float4 v = vals[rr][t];
                int i = lane + 32 * t;
                dst[2 * i]     = __floats2bfloat162_rn(v.x, v.y);
                dst[2 * i + 1] = __floats2bfloat162_rn(v.z, v.w);
            }
            if (lane == 0) sinv[p] = 1.0f / fmaxf(sqrtf(sums[rr]), 1e-12f);
        }
    }
    __syncthreads();

    float tb = targets[b];
    if (w < 4) {
        // gram: warp w owns k-slice [128w, 128w+128), 32x32 raw gram
        uint32_t base = (uint32_t)__cvta_generic_to_shared(pfh);
        int kslice = w * 128;
        int w8 = lane & 7;
        uint32_t aAddr[2], bAddr[2];
#pragma unroll
        for (int m = 0; m < 2; m++) {
            int row  = 16 * m + ((lane >> 3) & 1) * 8 + w8;
            int koff = (lane >> 4) * 8;
            aAddr[m] = base + (uint32_t)(row * SPW + kslice + koff) * 2;
        }
#pragma unroll
        for (int p = 0; p < 2; p++) {
            int col  = 16 * p + ((lane >> 4) & 1) * 8 + w8;
            int koff = ((lane >> 3) & 1) * 8;
            bAddr[p] = base + (uint32_t)(col * SPW + kslice + koff) * 2;
        }
        float acc[2][4][4] = {};
#pragma unroll
        for (int ks = 0; ks < 8; ks++) {
            uint32_t a[2][4], bb[2][4];
#pragma unroll
            for (int m = 0; m < 2; m++) ldsm4(a[m], aAddr[m] + ks * 32);
#pragma unroll
            for (int p = 0; p < 2; p++) ldsm4(bb[p], bAddr[p] + ks * 32);
#pragma unroll
            for (int m = 0; m < 2; m++) {
#pragma unroll
                for (int n = 0; n < 4; n++) {
                    mma_bf16(acc[m][n], a[m], bb[n >> 1][(n & 1) * 2],
                             bb[n >> 1][(n & 1) * 2 + 1]);
                }
            }
        }
        float* my = part + w * 1024;
#pragma unroll
        for (int m = 0; m < 2; m++) {
#pragma unroll
            for (int n = 0; n < 4; n++) {
                int r0 = 16 * m + (lane >> 2);
                int c0 = 8 * n + 2 * (lane & 3);
                my[r0 * 32 + c0]           = acc[m][n][0];
                my[r0 * 32 + c0 + 1]       = acc[m][n][1];
                my[(r0 + 8) * 32 + c0]     = acc[m][n][2];
                my[(r0 + 8) * 32 + c0 + 1] = acc[m][n][3];
            }
        }
    } else {
        // it-dots: warp w (4..7) handles pivots (w-4)*8 .. (w-4)*8+7
        const uint32_t* fr2 = (const uint32_t*)fr;
        float itv = 0.f;
#pragma unroll
        for (int r = 0; r < 8; r++) {
            int p = (w - 4) * 8 + r;
            const uint32_t* pf2 = (const uint32_t*)(pfh + p * SPW);
            float s = 0.f;
#pragma unroll
            for (int t = 0; t < 8; t++) {
                float2 a2 = __bfloat1622float2(*(const __nv_bfloat162*)&fr2[lane + 32 * t]);
                float2 b2 = __bfloat1622float2(*(const __nv_bfloat162*)&pf2[lane + 32 * t]);
                s += a2.x * b2.x + a2.y * b2.y;
            }
            s = warp_sum(s);
            if (lane == 0)
                itv += fabsf(s * sinv[p] - (1.f - 0.1f * fabsf(tb - ps_s[p])));
        }
        if (lane == 0) red[8 + (w - 4)] = itv;
    }
    __syncthreads();

    // epilogue: sum 4 partials, scale by inv_p*inv_q, tt loss
    float tt = 0.f;
#pragma unroll
    for (int k = 0; k < 4; k++) {
        int e = tid + 256 * k;  // 0..1023
        int p = e >> 5, q = e & 31;
        float s = (part[e] + part[1024 + e] + part[2048 + e] + part[3072 + e])
                * sinv[p] * sinv[q];
        tt += fabsf(s - (1.f - 0.1f * fabsf(ps_s[p] - ps_s[q])));
    }
    tt = warp_sum(tt);
    if (lane == 0) red[w] = tt;
    __syncthreads();
    if (tid == 0) {
        float t0 = 0.f, t1 = 0.f;
#pragma unroll
        for (int i = 0; i < 8; i++) t0 += red[i];
#pragma unroll
        for (int i = 0; i < 4; i++) t1 += red[8 + i];
        atomicAdd(&g_acc[1], (double)t0);
        atomicAdd(&g_acc[2], (double)t1);
        atomicAdd(&g_acc[3], (double)fabsf(pred[b] - tb));   // mae term
    }
}

// ---------------- ii body (one block per 128x128 tile) ----------------
__device__ __forceinline__ void ii_body(int tileIdx, char* smraw,
                                        const float* __restrict__ targets) {
    __nv_bfloat16* sm = (__nv_bfloat16*)smraw;   // As0|As1|Bs0|Bs1
    __shared__ float tr[128], tc[128], red2[8];

    int idx = tileIdx, bi = 0;
    while (true) {
        int len = NT2 - bi;
        if (idx < len) break;
        idx -= len; bi++;
    }
    int bj = bi + idx;

    int tid = threadIdx.x, lane = tid & 31, w = tid >> 5;
    if (tid < 128) tr[tid]       = targets[bi * 128 + tid];
    else           tc[tid - 128] = targets[bj * 128 + (tid - 128)];

    uint32_t smBase = (uint32_t)__cvta_generic_to_shared(sm);
    const __nv_bfloat16* Ag = g_fnh + (size_t)(bi * 128) * NC;
    const __nv_bfloat16* Bg = g_fnh + (size_t)(bj * 128) * NC;

    int crow[4], cch[4];
#pragma unroll
    for (int i = 0; i < 4; i++) {
        int c = tid + 256 * i;
        crow[i] = c >> 3;
        cch[i]  = (c & 7) * 8;
    }

    int wy = w >> 1, wx = w & 1;   // warp grid 4x2, warp tile 32x64
    int w8 = lane & 7;
    uint32_t aOff[2], bOff[4];
#pragma unroll
    for (int m = 0; m < 2; m++) {
        int row  = 32 * wy + 16 * m + ((lane >> 3) & 1) * 8 + w8;
        int koff = (lane >> 4) * 8;
        aOff[m] = (uint32_t)(row * SAW + koff) * 2;
    }
#pragma unroll
    for (int p = 0; p < 4; p++) {
        int col  = 64 * wx + 16 * p + ((lane >> 4) & 1) * 8 + w8;
        int koff = ((lane >> 3) & 1) * 8;
        bOff[p] = (uint32_t)(col * SAW + koff) * 2;
    }

#pragma unroll
    for (int s = 0; s < 2; s++) {
        uint32_t abase = smBase + s * BUFSZ;
        uint32_t bbase = smBase + 2 * BUFSZ + s * BUFSZ;
        int k0 = s * 64;
#pragma unroll
        for (int i = 0; i < 4; i++) {
            cp16(abase + (uint32_t)(crow[i] * SAW + cch[i]) * 2,
                 Ag + (size_t)crow[i] * NC + k0 + cch[i]);
            cp16(bbase + (uint32_t)(crow[i] * SAW + cch[i]) * 2,
                 Bg + (size_t)crow[i] * NC + k0 + cch[i]);
        }
        CP_COMMIT();
    }

    float acc[2][8][4] = {};
#pragma unroll
    for (int k0 = 0; k0 < 8; k0++) {
        if (k0 == 7) { CP_WAIT(0); } else { CP_WAIT(1); }
        __syncthreads();
        int buf = k0 & 1;
        uint32_t abase = smBase + buf * BUFSZ;
        uint32_t bbase = smBase + 2 * BUFSZ + buf * BUFSZ;
#pragma unroll
        for (int ks = 0; ks < 4; ks++) {
            uint32_t a[2][4], bb[4][4];
#pragma unroll
            for (int m = 0; m < 2; m++) ldsm4(a[m], abase + aOff[m] + ks * 32);
#pragma unroll
            for (int p = 0; p < 4; p++) ldsm4(bb[p], bbase + bOff[p] + ks * 32);
#pragma unroll
            for (int m = 0; m < 2; m++) {
#pragma unroll
                for (int n = 0; n < 8; n++) {
                    mma_bf16(acc[m][n], a[m], bb[n >> 1][(n & 1) * 2],
                             bb[n >> 1][(n & 1) * 2 + 1]);
                }
            }
        }
        __syncthreads();
        if (k0 + 2 < 8) {
            int s = k0 + 2, kk = s * 64, nbuf = s & 1;
            uint32_t na = smBase + nbuf * BUFSZ;
            uint32_t nb = smBase + 2 * BUFSZ + nbuf * BUFSZ;
#pragma unroll
            for (int i = 0; i < 4; i++) {
                cp16(na + (uint32_t)(crow[i] * SAW + cch[i]) * 2,
                     Ag + (size_t)crow[i] * NC + kk + cch[i]);
                cp16(nb + (uint32_t)(crow[i] * SAW + cch[i]) * 2,
                     Bg + (size_t)crow[i] * NC + kk + cch[i]);
            }
            CP_COMMIT();
        }
    }

    float lsum = 0.f;
#pragma unroll
    for (int m = 0; m < 2; m++) {
#pragma unroll
        for (int n = 0; n < 8; n++) {
            int r0 = 32 * wy + 16 * m + (lane >> 2);
            int c0 = 64 * wx + 8 * n + 2 * (lane & 3);
            float tr0 = tr[r0], tr8 = tr[r0 + 8];
            float tc0 = tc[c0], tc1 = tc[c0 + 1];
            lsum += fabsf(acc[m][n][0] - (1.f - 0.1f * fabsf(tr0 - tc0)));
            lsum += fabsf(acc[m][n][1] - (1.f - 0.1f * fabsf(tr0 - tc1)));
            lsum += fabsf(acc[m][n][2] - (1.f - 0.1f * fabsf(tr8 - tc0)));
            lsum += fabsf(acc[m][n][3] - (1.f - 0.1f * fabsf(tr8 - tc1)));
        }
    }
    lsum = warp_sum(lsum);
    if (lane == 0) red2[w] = lsum;
    __syncthreads();
    if (tid == 0) {
        float wgt = (bi == bj) ? 1.f : 2.f;
        float t0 = 0.f;
#pragma unroll
        for (int i = 0; i < 8; i++) t0 += red2[i];
        atomicAdd(&g_acc[0], (double)(t0 * wgt));
    }
}

// Merged kernel: ii tiles interleaved 1-in-8 with pivot blocks; the block
// that finishes last writes the 4 outputs. Fence is thread-0-only (release
// before g_cnt; acquire in the winning block) — NOT block-wide.
__global__ void __launch_bounds__(256, 2) k_work(const float* __restrict__ pf,
                                                 const float* __restrict__ ps,
                                                 const float* __restrict__ targets,
                                                 const float* __restrict__ pred,
                                                 float* __restrict__ out) {
    extern __shared__ char smraw[];
    int bid = blockIdx.x;
    int iiId = bid >> 3;
    if ((bid & 7) == 7 && iiId < NBLK_II) {
        ii_body(iiId, smraw, targets);
    } else {
        int nIIBefore = (bid + 1) >> 3;
        if (nIIBefore > NBLK_II) nIIBefore = NBLK_II;
        int pid = bid - nIIBefore;
        pivot_body(pid, smraw, pf, ps, targets, pred);
    }

    // last-block-done epilogue (only tid 0 issued this block's global atomics)
    if (threadIdx.x == 0) {
        __threadfence();                               // release own g_acc adds
        unsigned int done = atomicAdd(&g_cnt, 1u);
        if (done == NWORK - 1) {
            __threadfence();                           // acquire others' g_acc adds
            double ii  = atomicAdd(&g_acc[0], 0.0);
            double tt  = atomicAdd(&g_acc[1], 0.0);
            double it  = atomicAdd(&g_acc[2], 0.0);
            double mae = atomicAdd(&g_acc[3], 0.0);
            out[0] = (float)(ii  / ((double)NB * (double)NB));
            out[1] = (float)(tt  / ((double)NB * (double)NP * (double)NP));
            out[2] = (float)(it  / ((double)NB * (double)NP));
            out[3] = (float)(mae / (double)NB);
            g_cnt = 0;   // self-reset for graph replay
        }
    }
}

extern "C" void kernel_launch(void* const* d_in, const int* in_sizes, int n_in,
                              void* d_out, int out_size) {
    const float* pred    = (const float*)d_in[0];
    const float* targets = (const float*)d_in[1];
    const float* feats   = (const float*)d_in[2];
    const float* pivf    = (const float*)d_in[3];
    const float* pivs    = (const float*)d_in[4];
    float* out = (float*)d_out;

    size_t smWork = (size_t)(4 * BUFSZ);   // 73728 bytes (ii needs all; pivot ~51KB)
    cudaFuncSetAttribute(k_work, cudaFuncAttributeMaxDynamicSharedMemorySize, (int)smWork);

    k_norm_feats<<<NB, 128>>>(feats);
    k_work<<<NWORK, 256, smWork>>>(pivf, pivs, targets, pred, out);
}

// round 17
// speedup vs baseline: 1.0619x; 1.0600x over previous
#include <cuda_runtime.h>
#include <cuda_bf16.h>
#include <stdint.h>
#include <math.h>

#define NB 4096
#define NP 32
#define NC 512
#define NT2 32                          // 4096/128 tile grid for ii
#define NBLK_II (NT2 * (NT2 + 1) / 2)   // 528 upper-triangle tiles
#define SAW 72                          // padded smem row (bf16) for ii tiles
#define BUFSZ (128 * SAW * 2)           // bytes per 128x64 bf16 buffer
#define SPW 520                         // padded smem row (bf16) for pivot matrix
#define NWORK (NB + NBLK_II)            // merged grid: 4624

__device__ double g_acc[4];                 // [0]=ii, [1]=tt, [2]=it, [3]=mae
__device__ __nv_bfloat16 g_fnh[NB * NC];    // L2-normalized feats, bf16

__device__ __forceinline__ float warp_sum(float v) {
#pragma unroll
    for (int o = 16; o > 0; o >>= 1) v += __shfl_xor_sync(0xffffffffu, v, o);
    return v;
}

__device__ __forceinline__ void ldsm4(uint32_t* r, uint32_t addr) {
    asm volatile("ldmatrix.sync.aligned.m8n8.x4.shared.b16 {%0,%1,%2,%3}, [%4];"
                 : "=r"(r[0]), "=r"(r[1]), "=r"(r[2]), "=r"(r[3]) : "r"(addr));
}

__device__ __forceinline__ void mma_bf16(float* d, const uint32_t* a,
                                         uint32_t b0, uint32_t b1) {
    asm volatile(
        "mma.sync.aligned.m16n8k16.row.col.f32.bf16.bf16.f32 "
        "{%0,%1,%2,%3}, {%4,%5,%6,%7}, {%8,%9}, {%0,%1,%2,%3};"
        : "+f"(d[0]), "+f"(d[1]), "+f"(d[2]), "+f"(d[3])
        : "r"(a[0]), "r"(a[1]), "r"(a[2]), "r"(a[3]), "r"(b0), "r"(b1));
}

__device__ __forceinline__ void cp16(uint32_t saddr, const void* gptr) {
    asm volatile("cp.async.cg.shared.global [%0], [%1], 16;"
                 :: "r"(saddr), "l"(gptr) : "memory");
}
#define CP_COMMIT() asm volatile("cp.async.commit_group;" ::: "memory")
#define CP_WAIT(N)  asm volatile("cp.async.wait_group %0;" :: "n"(N) : "memory")

// One block per feats row: L2-normalize, write bf16 row. tid 0 also folds
// this row's mae term into g_acc[3] (g_acc is zeroed by the PREVIOUS
// k_final, stream-ordered — no race with these atomics).
__global__ void k_norm_feats(const float* __restrict__ feats,
                             const float* __restrict__ pred,
                             const float* __restrict__ targets) {
    __shared__ float red[4];
    int b = blockIdx.x, t = threadIdx.x;  // 128 threads, 128 float4/row
    const float4* src = (const float4*)(feats + (size_t)b * NC);
    float4 v = src[t];
    float s = v.x * v.x + v.y * v.y + v.z * v.z + v.w * v.w;
    s = warp_sum(s);
    if ((t & 31) == 0) red[t >> 5] = s;
    if (t == 0) atomicAdd(&g_acc[3], (double)fabsf(pred[b] - targets[b]));
    __syncthreads();
    float tot = red[0] + red[1] + red[2] + red[3];
    float inv = 1.0f / fmaxf(sqrtf(tot), 1e-12f);
    __nv_bfloat162* dst = (__nv_bfloat162*)(g_fnh + (size_t)b * NC);
    dst[2 * t]     = __floats2bfloat162_rn(v.x * inv, v.y * inv);
    dst[2 * t + 1] = __floats2bfloat162_rn(v.z * inv, v.w * inv);
}

// ---------------- pivot body (one block per batch b) ----------------
__device__ __forceinline__ void pivot_body(int b, char* smraw,
                                           const float* __restrict__ pf,
                                           const float* __restrict__ ps,
                                           const float* __restrict__ targets) {
    __nv_bfloat16* pfh = (__nv_bfloat16*)smraw;                  // 32 * SPW raw bf16
    __nv_bfloat16* fr  = (__nv_bfloat16*)(smraw + 32 * SPW * 2); // 512 normalized feat row
    float* part = (float*)(smraw + 32 * SPW * 2 + NC * 2);       // 4 * 1024
    float* ps_s = part + 4096;                                   // 32
    float* sinv = ps_s + 32;                                     // 32
    float* red  = sinv + 32;                                     // 16

    int tid = threadIdx.x, lane = tid & 31, w = tid >> 5;

    if (tid < 32) ps_s[tid] = ps[b * NP + tid];
    if (tid < 64)
        ((uint4*)fr)[tid] = ((const uint4*)(g_fnh + (size_t)b * NC))[tid];

    // load pivot rows raw (all 16 LDG.128 upfront), norms, store bf16 + sinv.
    {
        float4 vals[4][4];
#pragma unroll
        for (int rr = 0; rr < 4; rr++) {
            int p = w + rr * 8;
            const float4* src4 = (const float4*)(pf + ((size_t)b * NP + p) * NC);
#pragma unroll
            for (int t = 0; t < 4; t++) vals[rr][t] = src4[lane + 32 * t];
        }
        float sums[4];
#pragma unroll
        for (int rr = 0; rr < 4; rr++) {
            float s = 0.f;
#pragma unroll
            for (int t = 0; t < 4; t++) {
                float4 v = vals[rr][t];
                s += v.x * v.x + v.y * v.y + v.z * v.z + v.w * v.w;
            }
            sums[rr] = warp_sum(s);
        }
#pragma unroll
        for (int rr = 0; rr < 4; rr++) {
            int p = w + rr * 8;
            __nv_bfloat162* dst = (__nv_bfloat162*)(pfh + p * SPW);
#pragma unroll
            for (int t = 0; t < 4; t++) {
                float4 v = vals[rr][t];
                int i = lane + 32 * t;
                dst[2 * i]     = __floats2bfloat162_rn(v.x, v.y);
                dst[2 * i + 1] = __floats2bfloat162_rn(v.z, v.w);
            }
            if (lane == 0) sinv[p] = 1.0f / fmaxf(sqrtf(sums[rr]), 1e-12f);
        }
    }
    __syncthreads();

    float tb = targets[b];
    if (w < 4) {
        // gram: warp w owns k-slice [128w, 128w+128), 32x32 raw gram
        uint32_t base = (uint32_t)__cvta_generic_to_shared(pfh);
        int kslice = w * 128;
        int w8 = lane & 7;
        uint32_t aAddr[2], bAddr[2];
#pragma unroll
        for (int m = 0; m < 2; m++) {
            int row  = 16 * m + ((lane >> 3) & 1) * 8 + w8;
            int koff = (lane >> 4) * 8;
            aAddr[m] = base + (uint32_t)(row * SPW + kslice + koff) * 2;
        }
#pragma unroll
        for (int p = 0; p < 2; p++) {
            int col  = 16 * p + ((lane >> 4) & 1) * 8 + w8;
            int koff = ((lane >> 3) & 1) * 8;
            bAddr[p] = base + (uint32_t)(col * SPW + kslice + koff) * 2;
        }
        float acc[2][4][4] = {};
#pragma unroll
        for (int ks = 0; ks < 8; ks++) {
            uint32_t a[2][4], bb[2][4];
#pragma unroll
            for (int m = 0; m < 2; m++) ldsm4(a[m], aAddr[m] + ks * 32);
#pragma unroll
            for (int p = 0; p < 2; p++) ldsm4(bb[p], bAddr[p] + ks * 32);
#pragma unroll
            for (int m = 0; m < 2; m++) {
#pragma unroll
                for (int n = 0; n < 4; n++) {
                    mma_bf16(acc[m][n], a[m], bb[n >> 1][(n & 1) * 2],
                             bb[n >> 1][(n & 1) * 2 + 1]);
                }
            }
        }
        float* my = part + w * 1024;
#pragma unroll
        for (int m = 0; m < 2; m++) {
#pragma unroll
            for (int n = 0; n < 4; n++) {
                int r0 = 16 * m + (lane >> 2);
                int c0 = 8 * n + 2 * (lane & 3);
                my[r0 * 32 + c0]           = acc[m][n][0];
                my[r0 * 32 + c0 + 1]       = acc[m][n][1];
                my[(r0 + 8) * 32 + c0]     = acc[m][n][2];
                my[(r0 + 8) * 32 + c0 + 1] = acc[m][n][3];
            }
        }
    } else {
        // it-dots: warp w (4..7) handles pivots (w-4)*8 .. (w-4)*8+7
        const uint32_t* fr2 = (const uint32_t*)fr;
        float itv = 0.f;
#pragma unroll
        for (int r = 0; r < 8; r++) {
            int p = (w - 4) * 8 + r;
            const uint32_t* pf2 = (const uint32_t*)(pfh + p * SPW);
            float s = 0.f;
#pragma unroll
            for (int t = 0; t < 8; t++) {
                float2 a2 = __bfloat1622float2(*(const __nv_bfloat162*)&fr2[lane + 32 * t]);
                float2 b2 = __bfloat1622float2(*(const __nv_bfloat162*)&pf2[lane + 32 * t]);
                s += a2.x * b2.x + a2.y * b2.y;
            }
            s = warp_sum(s);
            if (lane == 0)
                itv += fabsf(s * sinv[p] - (1.f - 0.1f * fabsf(tb - ps_s[p])));
        }
        if (lane == 0) red[8 + (w - 4)] = itv;
    }
    __syncthreads();

    // epilogue: sum 4 partials, scale by inv_p*inv_q, tt loss
    float tt = 0.f;
#pragma unroll
    for (int k = 0; k < 4; k++) {
        int e = tid + 256 * k;  // 0..1023
        int p = e >> 5, q = e & 31;
        float s = (part[e] + part[1024 + e] + part[2048 + e] + part[3072 + e])
                * sinv[p] * sinv[q];
        tt += fabsf(s - (1.f - 0.1f * fabsf(ps_s[p] - ps_s[q])));
    }
    tt = warp_sum(tt);
    if (lane == 0) red[w] = tt;
    __syncthreads();
    if (tid == 0) {
        float t0 = 0.f, t1 = 0.f;
#pragma unroll
        for (int i = 0; i < 8; i++) t0 += red[i];
#pragma unroll
        for (int i = 0; i < 4; i++) t1 += red[8 + i];
        atomicAdd(&g_acc[1], (double)t0);
        atomicAdd(&g_acc[2], (double)t1);
    }
}

// ---------------- ii body (one block per 128x128 tile) ----------------
__device__ __forceinline__ void ii_body(int tileIdx, char* smraw,
                                        const float* __restrict__ targets) {
    __nv_bfloat16* sm = (__nv_bfloat16*)smraw;   // As0|As1|Bs0|Bs1
    __shared__ float tr[128], tc[128], red2[8];

    int idx = tileIdx, bi = 0;
    while (true) {
        int len = NT2 - bi;
        if (idx < len) break;
        idx -= len; bi++;
    }
    int bj = bi + idx;

    int tid = threadIdx.x, lane = tid & 31, w = tid >> 5;
    if (tid < 128) tr[tid]       = targets[bi * 128 + tid];
    else           tc[tid - 128] = targets[bj * 128 + (tid - 128)];

    uint32_t smBase = (uint32_t)__cvta_generic_to_shared(sm);
    const __nv_bfloat16* Ag = g_fnh + (size_t)(bi * 128) * NC;
    const __nv_bfloat16* Bg = g_fnh + (size_t)(bj * 128) * NC;

    int crow[4], cch[4];
#pragma unroll
    for (int i = 0; i < 4; i++) {
        int c = tid + 256 * i;
        crow[i] = c >> 3;
        cch[i]  = (c & 7) * 8;
    }

    int wy = w >> 1, wx = w & 1;   // warp grid 4x2, warp tile 32x64
    int w8 = lane & 7;
    uint32_t aOff[2], bOff[4];
#pragma unroll
    for (int m = 0; m < 2; m++) {
        int row  = 32 * wy + 16 * m + ((lane >> 3) & 1) * 8 + w8;
        int koff = (lane >> 4) * 8;
        aOff[m] = (uint32_t)(row * SAW + koff) * 2;
    }
#pragma unroll
    for (int p = 0; p < 4; p++) {
        int col  = 64 * wx + 16 * p + ((lane >> 4) & 1) * 8 + w8;
        int koff = ((lane >> 3) & 1) * 8;
        bOff[p] = (uint32_t)(col * SAW + koff) * 2;
    }

#pragma unroll
    for (int s = 0; s < 2; s++) {
        uint32_t abase = smBase + s * BUFSZ;
        uint32_t bbase = smBase + 2 * BUFSZ + s * BUFSZ;
        int k0 = s * 64;
#pragma unroll
        for (int i = 0; i < 4; i++) {
            cp16(abase + (uint32_t)(crow[i] * SAW + cch[i]) * 2,
                 Ag + (size_t)crow[i] * NC + k0 + cch[i]);
            cp16(bbase + (uint32_t)(crow[i] * SAW + cch[i]) * 2,
                 Bg + (size_t)crow[i] * NC + k0 + cch[i]);
        }
        CP_COMMIT();
    }

    float acc[2][8][4] = {};
#pragma unroll
    for (int k0 = 0; k0 < 8; k0++) {
        if (k0 == 7) { CP_WAIT(0); } else { CP_WAIT(1); }
        __syncthreads();
        int buf = k0 & 1;
        uint32_t abase = smBase + buf * BUFSZ;
        uint32_t bbase = smBase + 2 * BUFSZ + buf * BUFSZ;
#pragma unroll
        for (int ks = 0; ks < 4; ks++) {
            uint32_t a[2][4], bb[4][4];
#pragma unroll
            for (int m = 0; m < 2; m++) ldsm4(a[m], abase + aOff[m] + ks * 32);
#pragma unroll
            for (int p = 0; p < 4; p++) ldsm4(bb[p], bbase + bOff[p] + ks * 32);
#pragma unroll
            for (int m = 0; m < 2; m++) {
#pragma unroll
                for (int n = 0; n < 8; n++) {
                    mma_bf16(acc[m][n], a[m], bb[n >> 1][(n & 1) * 2],
                             bb[n >> 1][(n & 1) * 2 + 1]);
                }
            }
        }
        __syncthreads();
        if (k0 + 2 < 8) {
            int s = k0 + 2, kk = s * 64, nbuf = s & 1;
            uint32_t na = smBase + nbuf * BUFSZ;
            uint32_t nb = smBase + 2 * BUFSZ + nbuf * BUFSZ;
#pragma unroll
            for (int i = 0; i < 4; i++) {
                cp16(na + (uint32_t)(crow[i] * SAW + cch[i]) * 2,
                     Ag + (size_t)crow[i] * NC + kk + cch[i]);
                cp16(nb + (uint32_t)(crow[i] * SAW + cch[i]) * 2,
                     Bg + (size_t)crow[i] * NC + kk + cch[i]);
            }
            CP_COMMIT();
        }
    }

    float lsum = 0.f;
#pragma unroll
    for (int m = 0; m < 2; m++) {
#pragma unroll
        for (int n = 0; n < 8; n++) {
            int r0 = 32 * wy + 16 * m + (lane >> 2);
            int c0 = 64 * wx + 8 * n + 2 * (lane & 3);
            float tr0 = tr[r0], tr8 = tr[r0 + 8];
            float tc0 = tc[c0], tc1 = tc[c0 + 1];
            lsum += fabsf(acc[m][n][0] - (1.f - 0.1f * fabsf(tr0 - tc0)));
            lsum += fabsf(acc[m][n][1] - (1.f - 0.1f * fabsf(tr0 - tc1)));
            lsum += fabsf(acc[m][n][2] - (1.f - 0.1f * fabsf(tr8 - tc0)));
            lsum += fabsf(acc[m][n][3] - (1.f - 0.1f * fabsf(tr8 - tc1)));
        }
    }
    lsum = warp_sum(lsum);
    if (lane == 0) red2[w] = lsum;
    __syncthreads();
    if (tid == 0) {
        float wgt = (bi == bj) ? 1.f : 2.f;
        float t0 = 0.f;
#pragma unroll
        for (int i = 0; i < 8; i++) t0 += red2[i];
        atomicAdd(&g_acc[0], (double)(t0 * wgt));
    }
}

// Merged kernel (R13 form): ii tiles interleaved 1-in-8 with pivot blocks.
__global__ void __launch_bounds__(256, 2) k_work(const float* __restrict__ pf,
                                                 const float* __restrict__ ps,
                                                 const float* __restrict__ targets) {
    extern __shared__ char smraw[];
    int bid = blockIdx.x;
    int iiId = bid >> 3;
    if ((bid & 7) == 7 && iiId < NBLK_II) {
        ii_body(iiId, smraw, targets);
    } else {
        int nIIBefore = (bid + 1) >> 3;
        if (nIIBefore > NBLK_II) nIIBefore = NBLK_II;
        int pid = bid - nIIBefore;
        pivot_body(pid, smraw, pf, ps, targets);
    }
}

// Tiny scalar tail: read accumulators, write 4 outputs, then re-zero the
// accumulators for the next graph replay (stream-ordered).
__global__ void k_final(float* __restrict__ out) {
    if (threadIdx.x == 0) {
        out[0] = (float)(g_acc[0] / ((double)NB * (double)NB));
        out[1] = (float)(g_acc[1] / ((double)NB * (double)NP * (double)NP));
        out[2] = (float)(g_acc[2] / ((double)NB * (double)NP));
        out[3] = (float)(g_acc[3] / (double)NB);
        g_acc[0] = 0.0; g_acc[1] = 0.0; g_acc[2] = 0.0; g_acc[3] = 0.0;
    }
}

extern "C" void kernel_launch(void* const* d_in, const int* in_sizes, int n_in,
                              void* d_out, int out_size) {
    const float* pred    = (const float*)d_in[0];
    const float* targets = (const float*)d_in[1];
    const float* feats   = (const float*)d_in[2];
    const float* pivf    = (const float*)d_in[3];
    const float* pivs    = (const float*)d_in[4];
    float* out = (float*)d_out;

    size_t smWork = (size_t)(4 * BUFSZ);   // 73728 bytes (ii needs all; pivot ~51KB)
    cudaFuncSetAttribute(k_work, cudaFuncAttributeMaxDynamicSharedMemorySize, (int)smWork);

    k_norm_feats<<<NB, 128>>>(feats, pred, targets);
    k_work<<<NWORK, 256, smWork>>>(pivf, pivs, targets);
    k_final<<<1, 32>>>(out);
}